// round 1
// baseline (speedup 1.0000x reference)
#include <cuda_runtime.h>
#include <math.h>

#define NN 50000
#define EE 800000
#define KDIM 128     // IN_DIM
#define CD 128       // H*D output cols
#define NH 8
#define HD 16

// ---------------- device scratch (no allocation allowed) ----------------
__device__ float g_Qh[(size_t)NN * CD];
__device__ float g_Kh[(size_t)NN * CD];
__device__ float g_Vh[(size_t)NN * CD];
__device__ float g_z[(size_t)NN * NH];

// ---------------- node projection GEMM: out = h @ W + b ----------------
// BM=64 rows x 128 cols, 256 threads, thread tile 4x8.
__global__ __launch_bounds__(256) void node_proj_kernel(
    const float* __restrict__ h,
    const float* __restrict__ W,
    const float* __restrict__ b,
    float* __restrict__ out)
{
    extern __shared__ float sm[];
    float* sW = sm;                 // 128*128
    float* sA = sm + KDIM * CD;     // 64*132 padded

    const int tid = threadIdx.x;
    const int r0  = blockIdx.x * 64;

    // load weights (coalesced float4)
    for (int i = tid; i < KDIM * CD / 4; i += 256) {
        reinterpret_cast<float4*>(sW)[i] = reinterpret_cast<const float4*>(W)[i];
    }
    // load A tile with row guard
    for (int i = tid; i < 64 * 32; i += 256) {
        int row = i >> 5, kc = i & 31;
        float4 v = make_float4(0.f, 0.f, 0.f, 0.f);
        int gr = r0 + row;
        if (gr < NN)
            v = reinterpret_cast<const float4*>(h + (size_t)gr * KDIM)[kc];
        *reinterpret_cast<float4*>(sA + row * 132 + kc * 4) = v;
    }
    __syncthreads();

    const int ty = tid >> 4, tx = tid & 15;
    const int c0 = tx * 8;
    const int ty4 = ty * 4;

    float acc[4][8];
#pragma unroll
    for (int i = 0; i < 4; ++i)
#pragma unroll
        for (int j = 0; j < 8; ++j) acc[i][j] = 0.f;

#pragma unroll 4
    for (int k = 0; k < KDIM; ++k) {
        float4 w0 = *reinterpret_cast<const float4*>(sW + k * CD + c0);
        float4 w1 = *reinterpret_cast<const float4*>(sW + k * CD + c0 + 4);
        float we[8] = {w0.x, w0.y, w0.z, w0.w, w1.x, w1.y, w1.z, w1.w};
#pragma unroll
        for (int i = 0; i < 4; ++i) {
            float a = sA[(ty4 + i) * 132 + k];
#pragma unroll
            for (int j = 0; j < 8; ++j) acc[i][j] = fmaf(a, we[j], acc[i][j]);
        }
    }

    float bb[8];
    {
        float4 b0 = *reinterpret_cast<const float4*>(b + c0);
        float4 b1 = *reinterpret_cast<const float4*>(b + c0 + 4);
        bb[0]=b0.x; bb[1]=b0.y; bb[2]=b0.z; bb[3]=b0.w;
        bb[4]=b1.x; bb[5]=b1.y; bb[6]=b1.z; bb[7]=b1.w;
    }
#pragma unroll
    for (int i = 0; i < 4; ++i) {
        int r = r0 + ty4 + i;
        if (r >= NN) continue;
        float4 o0, o1;
        o0.x = acc[i][0] + bb[0]; o0.y = acc[i][1] + bb[1];
        o0.z = acc[i][2] + bb[2]; o0.w = acc[i][3] + bb[3];
        o1.x = acc[i][4] + bb[4]; o1.y = acc[i][5] + bb[5];
        o1.z = acc[i][6] + bb[6]; o1.w = acc[i][7] + bb[7];
        reinterpret_cast<float4*>(out + (size_t)r * CD + c0)[0] = o0;
        reinterpret_cast<float4*>(out + (size_t)r * CD + c0 + 4)[0] = o1;
    }
}

// ---------------- fused edge kernel ----------------
// Per block: 64 edges. Computes proj_e = e@Ew+Eb and proj_kr = kr@Rw+Rb
// (dual GEMM, weights in smem), then edge-wise score/exp, writes e_out,
// scatters wV (into out_h) and z (g_z) with atomics.
__global__ __launch_bounds__(256) void edge_kernel(
    const float* __restrict__ e,
    const float* __restrict__ kr,
    const int*  __restrict__ src,
    const int*  __restrict__ dst,
    const float* __restrict__ Ew, const float* __restrict__ Eb,
    const float* __restrict__ Rw, const float* __restrict__ Rb,
    float* __restrict__ out_h,     // wV accumulator (d_out, zeroed)
    float* __restrict__ out_e)     // e_out region
{
    extern __shared__ float sm[];
    float* sEw = sm;                          // 128*128
    float* sRw = sEw + KDIM * CD;             // 128*128
    float* sAe = sRw + KDIM * CD;             // 64*132
    float* sAk = sAe + 64 * 132;              // 64*132
    int*   sidx = reinterpret_cast<int*>(sAk + 64 * 132);  // 64 src + 64 dst

    const int tid = threadIdx.x;
    const int r0  = blockIdx.x * 64;

    for (int i = tid; i < KDIM * CD / 4; i += 256) {
        reinterpret_cast<float4*>(sEw)[i] = reinterpret_cast<const float4*>(Ew)[i];
        reinterpret_cast<float4*>(sRw)[i] = reinterpret_cast<const float4*>(Rw)[i];
    }
    for (int i = tid; i < 64 * 32; i += 256) {
        int row = i >> 5, kc = i & 31;
        float4 ve = reinterpret_cast<const float4*>(e  + (size_t)(r0 + row) * KDIM)[kc];
        float4 vk = reinterpret_cast<const float4*>(kr + (size_t)(r0 + row) * KDIM)[kc];
        *reinterpret_cast<float4*>(sAe + row * 132 + kc * 4) = ve;
        *reinterpret_cast<float4*>(sAk + row * 132 + kc * 4) = vk;
    }
    if (tid < 64) {
        sidx[tid]      = src[r0 + tid];
        sidx[64 + tid] = dst[r0 + tid];
    }
    __syncthreads();

    const int ty = tid >> 4, tx = tid & 15;
    const int c0 = tx * 8;
    const int ty4 = ty * 4;
    const int head = tx >> 1;

    float accE[4][8], accR[4][8];
#pragma unroll
    for (int i = 0; i < 4; ++i)
#pragma unroll
        for (int j = 0; j < 8; ++j) { accE[i][j] = 0.f; accR[i][j] = 0.f; }

#pragma unroll 4
    for (int k = 0; k < KDIM; ++k) {
        float4 w0 = *reinterpret_cast<const float4*>(sEw + k * CD + c0);
        float4 w1 = *reinterpret_cast<const float4*>(sEw + k * CD + c0 + 4);
        float4 u0 = *reinterpret_cast<const float4*>(sRw + k * CD + c0);
        float4 u1 = *reinterpret_cast<const float4*>(sRw + k * CD + c0 + 4);
        float we[8] = {w0.x, w0.y, w0.z, w0.w, w1.x, w1.y, w1.z, w1.w};
        float wr[8] = {u0.x, u0.y, u0.z, u0.w, u1.x, u1.y, u1.z, u1.w};
#pragma unroll
        for (int i = 0; i < 4; ++i) {
            float a = sAe[(ty4 + i) * 132 + k];
            float b = sAk[(ty4 + i) * 132 + k];
#pragma unroll
            for (int j = 0; j < 8; ++j) {
                accE[i][j] = fmaf(a, we[j], accE[i][j]);
                accR[i][j] = fmaf(b, wr[j], accR[i][j]);
            }
        }
    }

    float eb[8], rb[8];
    {
        float4 b0 = *reinterpret_cast<const float4*>(Eb + c0);
        float4 b1 = *reinterpret_cast<const float4*>(Eb + c0 + 4);
        eb[0]=b0.x; eb[1]=b0.y; eb[2]=b0.z; eb[3]=b0.w;
        eb[4]=b1.x; eb[5]=b1.y; eb[6]=b1.z; eb[7]=b1.w;
        float4 c0v = *reinterpret_cast<const float4*>(Rb + c0);
        float4 c1v = *reinterpret_cast<const float4*>(Rb + c0 + 4);
        rb[0]=c0v.x; rb[1]=c0v.y; rb[2]=c0v.z; rb[3]=c0v.w;
        rb[4]=c1v.x; rb[5]=c1v.y; rb[6]=c1v.z; rb[7]=c1v.w;
    }

#pragma unroll
    for (int i = 0; i < 4; ++i) {
        const int r   = r0 + ty4 + i;          // edge index (E multiple of 64)
        const int sn  = sidx[ty4 + i];
        const int dn  = sidx[64 + ty4 + i];

        const float4* Kp = reinterpret_cast<const float4*>(g_Kh + (size_t)sn * CD + c0);
        const float4* Qp = reinterpret_cast<const float4*>(g_Qh + (size_t)dn * CD + c0);
        const float4* Vp = reinterpret_cast<const float4*>(g_Vh + (size_t)sn * CD + c0);
        float4 K0 = Kp[0], K1 = Kp[1];
        float4 Q0 = Qp[0], Q1 = Qp[1];
        float4 V0 = Vp[0], V1 = Vp[1];

        float kk[8] = {K0.x, K0.y, K0.z, K0.w, K1.x, K1.y, K1.z, K1.w};
        float qq[8] = {Q0.x, Q0.y, Q0.z, Q0.w, Q1.x, Q1.y, Q1.z, Q1.w};
        float vv[8] = {V0.x, V0.y, V0.z, V0.w, V1.x, V1.y, V1.z, V1.w};

        float sc[8];
        float part = 0.f;
#pragma unroll
        for (int j = 0; j < 8; ++j) {
            float t = fmaf(kk[j] * qq[j], 0.25f, accR[i][j] + rb[j]);
            t = t * (accE[i][j] + eb[j]);
            sc[j] = t;
            part += t;
        }

        float4 o0 = make_float4(sc[0], sc[1], sc[2], sc[3]);
        float4 o1 = make_float4(sc[4], sc[5], sc[6], sc[7]);
        reinterpret_cast<float4*>(out_e + (size_t)r * CD + c0)[0] = o0;
        reinterpret_cast<float4*>(out_e + (size_t)r * CD + c0 + 4)[0] = o1;

        float tot = part + __shfl_xor_sync(0xffffffffu, part, 1);
        tot = fminf(fmaxf(tot, -5.0f), 5.0f);
        float sval = expf(tot);

        float* w = out_h + (size_t)dn * CD + c0;
#pragma unroll
        for (int j = 0; j < 8; ++j) atomicAdd(w + j, vv[j] * sval);
        if ((tx & 1) == 0) atomicAdd(&g_z[(size_t)dn * NH + head], sval);
    }
}

// ---------------- finalize: h_out = wV / (z + 1e-6) ----------------
__global__ __launch_bounds__(256) void finalize_kernel(float* __restrict__ out_h)
{
    int i = blockIdx.x * 256 + threadIdx.x;        // float4 index
    const int total = NN * CD / 4;
    if (i >= total) return;
    int n  = i >> 5;            // /32 float4s per node
    int cg = i & 31;            // float4 group within node
    int head = cg >> 2;         // 4 float4s per head
    float z = g_z[(size_t)n * NH + head] + 1e-6f;
    float inv = 1.0f / z;
    float4 v = reinterpret_cast<float4*>(out_h)[i];
    v.x *= inv; v.y *= inv; v.z *= inv; v.w *= inv;
    reinterpret_cast<float4*>(out_h)[i] = v;
}

// ---------------- launch ----------------
extern "C" void kernel_launch(void* const* d_in, const int* in_sizes, int n_in,
                              void* d_out, int out_size)
{
    const float* h   = (const float*)d_in[0];
    const float* e   = (const float*)d_in[1];
    const float* kr  = (const float*)d_in[2];
    const int*   src = (const int*)  d_in[3];
    const int*   dst = (const int*)  d_in[4];
    const float* Qw  = (const float*)d_in[5];
    const float* Qb  = (const float*)d_in[6];
    const float* Kw  = (const float*)d_in[7];
    const float* Kb  = (const float*)d_in[8];
    const float* Vw  = (const float*)d_in[9];
    const float* Vb  = (const float*)d_in[10];
    const float* Ew  = (const float*)d_in[11];
    const float* Eb  = (const float*)d_in[12];
    const float* Rw  = (const float*)d_in[13];
    const float* Rb  = (const float*)d_in[14];

    float* out_h = (float*)d_out;                       // [N, 128] wV/h_out
    float* out_e = (float*)d_out + (size_t)NN * CD;     // [E, 128] e_out

    const size_t NODE_SMEM = (size_t)(KDIM * CD + 64 * 132) * 4;                    // ~99 KB
    const size_t EDGE_SMEM = (size_t)(2 * KDIM * CD + 2 * 64 * 132) * 4 + 128 * 4;  // ~195 KB

    cudaFuncSetAttribute(node_proj_kernel, cudaFuncAttributeMaxDynamicSharedMemorySize, (int)NODE_SMEM);
    cudaFuncSetAttribute(edge_kernel,      cudaFuncAttributeMaxDynamicSharedMemorySize, (int)EDGE_SMEM);

    // zero accumulators (graph-capturable async memsets)
    cudaMemsetAsync(out_h, 0, (size_t)NN * CD * sizeof(float));
    void* zp = nullptr;
    cudaGetSymbolAddress(&zp, g_z);
    cudaMemsetAsync(zp, 0, (size_t)NN * NH * sizeof(float));

    void *qp, *kp, *vp;
    cudaGetSymbolAddress(&qp, g_Qh);
    cudaGetSymbolAddress(&kp, g_Kh);
    cudaGetSymbolAddress(&vp, g_Vh);

    const int nodeBlocks = (NN + 63) / 64;  // 782
    node_proj_kernel<<<nodeBlocks, 256, NODE_SMEM>>>(h, Qw, Qb, (float*)qp);
    node_proj_kernel<<<nodeBlocks, 256, NODE_SMEM>>>(h, Kw, Kb, (float*)kp);
    node_proj_kernel<<<nodeBlocks, 256, NODE_SMEM>>>(h, Vw, Vb, (float*)vp);

    const int edgeBlocks = EE / 64;         // 12500
    edge_kernel<<<edgeBlocks, 256, EDGE_SMEM>>>(e, kr, src, dst, Ew, Eb, Rw, Rb, out_h, out_e);

    const int finBlocks = (NN * CD / 4 + 255) / 256;
    finalize_kernel<<<finBlocks, 256>>>(out_h);
}